// round 3
// baseline (speedup 1.0000x reference)
#include <cuda_runtime.h>
#include <cuda_bf16.h>
#include <cstdint>
#include <cstddef>

#define SEQ 4096
#define DIM 1024
#define BM 128
#define BN 256
#define BK 64
#define NSTAGE 3
#define SMEM_A_BYTES (BM * 128)
#define SMEM_B_BYTES (BN * 128)
#define STAGE_BYTES (SMEM_A_BYTES + SMEM_B_BYTES)
#define SMEM_TOTAL (1024 + NSTAGE * STAGE_BYTES)

__device__ __align__(256) __nv_bfloat16 g_Qhi[(size_t)SEQ * DIM];
__device__ __align__(256) __nv_bfloat16 g_Qlo[(size_t)SEQ * DIM];
__device__ __align__(256) __nv_bfloat16 g_Khi[(size_t)SEQ * DIM];
__device__ __align__(256) __nv_bfloat16 g_Klo[(size_t)SEQ * DIM];
__device__ __align__(256) __nv_bfloat16 g_Vthi[(size_t)DIM * SEQ];
__device__ __align__(256) __nv_bfloat16 g_Vtlo[(size_t)DIM * SEQ];
__device__ __align__(256) float g_S[(size_t)SEQ * SEQ];
__device__ __align__(256) __nv_bfloat16 g_Phi[(size_t)SEQ * SEQ];
__device__ __align__(256) __nv_bfloat16 g_Plo[(size_t)SEQ * SEQ];

__device__ __forceinline__ uint32_t smem_u32(const void* p) {
    uint32_t a;
    asm("{ .reg .u64 t; cvta.to.shared.u64 t, %1; cvt.u32.u64 %0, t; }" : "=r"(a) : "l"(p));
    return a;
}
__device__ __forceinline__ uint32_t swz(uint32_t b) { return b ^ ((b >> 3) & 0x70u); }
__device__ __forceinline__ void cp16(uint32_t dst, const void* src) {
    asm volatile("cp.async.cg.shared.global [%0], [%1], 16;" :: "r"(dst), "l"(src));
}
__device__ __forceinline__ void cp_commit() { asm volatile("cp.async.commit_group;"); }
template <int N> __device__ __forceinline__ void cp_wait() {
    asm volatile("cp.async.wait_group %0;" :: "n"(N));
}
__device__ __forceinline__ void ldsm4(uint32_t* r, uint32_t a) {
    asm volatile("ldmatrix.sync.aligned.m8n8.x4.shared.b16 {%0,%1,%2,%3}, [%4];"
                 : "=r"(r[0]), "=r"(r[1]), "=r"(r[2]), "=r"(r[3]) : "r"(a));
}
__device__ __forceinline__ void mma16816(float* c, const uint32_t* a, const uint32_t* b) {
    asm volatile(
        "mma.sync.aligned.m16n8k16.row.col.f32.bf16.bf16.f32 "
        "{%0,%1,%2,%3}, {%4,%5,%6,%7}, {%8,%9}, {%0,%1,%2,%3};"
        : "+f"(c[0]), "+f"(c[1]), "+f"(c[2]), "+f"(c[3])
        : "r"(a[0]), "r"(a[1]), "r"(a[2]), "r"(a[3]), "r"(b[0]), "r"(b[1]));
}

__global__ __launch_bounds__(256) void split_kernel(const float* __restrict__ X, int which) {
    __nv_bfloat16* hi = which ? g_Khi : g_Qhi;
    __nv_bfloat16* lo = which ? g_Klo : g_Qlo;
    size_t i = (size_t)blockIdx.x * 256 + threadIdx.x;
    float4 x = reinterpret_cast<const float4*>(X)[i];
    float xs[4] = {x.x, x.y, x.z, x.w};
    uint32_t hw[4], lw[4];
#pragma unroll
    for (int k = 0; k < 4; k++) {
        __nv_bfloat16 h = __float2bfloat16(xs[k]);
        __nv_bfloat16 l = __float2bfloat16(xs[k] - __bfloat162float(h));
        hw[k] = __bfloat16_as_ushort(h);
        lw[k] = __bfloat16_as_ushort(l);
    }
    reinterpret_cast<uint2*>(hi)[i] = make_uint2(hw[0] | (hw[1] << 16), hw[2] | (hw[3] << 16));
    reinterpret_cast<uint2*>(lo)[i] = make_uint2(lw[0] | (lw[1] << 16), lw[2] | (lw[3] << 16));
}

__global__ __launch_bounds__(256) void transpose_split_kernel(const float* __restrict__ V) {
    __shared__ float tile[32][33];
    int tx = threadIdx.x & 31, ty = threadIdx.x >> 5;
    int d0 = blockIdx.x * 32, s0 = blockIdx.y * 32;
#pragma unroll
    for (int j = 0; j < 4; j++)
        tile[ty + j * 8][tx] = V[(size_t)(s0 + ty + j * 8) * DIM + d0 + tx];
    __syncthreads();
#pragma unroll
    for (int j = 0; j < 4; j++) {
        int r = ty + j * 8;
        float x = tile[tx][r];
        __nv_bfloat16 h = __float2bfloat16(x);
        __nv_bfloat16 l = __float2bfloat16(x - __bfloat162float(h));
        size_t o = (size_t)(d0 + r) * SEQ + s0 + tx;
        g_Vthi[o] = h;
        g_Vtlo[o] = l;
    }
}

// mode 0: S = Qhi*Khi^T + Qhi*Klo^T + Qlo*Khi^T   (K-extent DIM)
// mode 1: O = Phi*Vthi^T + Phi*Vtlo^T + Plo*Vthi^T (K-extent SEQ)
__global__ __launch_bounds__(256, 1) void gemm_split_kernel(int mode, float* Cout) {
    extern __shared__ __align__(16) char dynsmem[];
    uint32_t sbase = (smem_u32(dynsmem) + 1023u) & ~1023u;
    const int tid = threadIdx.x;
    const int warp = tid >> 5, lane = tid & 31;
    const int wm = (warp & 1) * 64;        // warp M offset (2 warps in M)
    const int wn = (warp >> 1) * 64;       // warp N offset (4 warps in N)
    const int Kseg = mode ? SEQ : DIM;
    const int segIters = Kseg / BK;
    const int NITER = 3 * segIters;
    const int m0 = blockIdx.y * BM;
    const int n0 = blockIdx.x * BN;
    const int ldc = mode ? DIM : SEQ;
    float* C = mode ? Cout : g_S;

    const __nv_bfloat16 *segA[3], *segB[3];
    if (mode == 0) {
        segA[0] = g_Qhi; segA[1] = g_Qhi; segA[2] = g_Qlo;
        segB[0] = g_Khi; segB[1] = g_Klo; segB[2] = g_Khi;
    } else {
        segA[0] = g_Phi; segA[1] = g_Phi; segA[2] = g_Plo;
        segB[0] = g_Vthi; segB[1] = g_Vtlo; segB[2] = g_Vthi;
    }

    auto load_it = [&](int it, int buf) {
        int seg = it / segIters;
        int kk = (it - seg * segIters) * BK;
        const __nv_bfloat16* Ap = segA[seg];
        const __nv_bfloat16* Bp = segB[seg];
        uint32_t sA = sbase + buf * STAGE_BYTES;
        uint32_t sB = sA + SMEM_A_BYTES;
#pragma unroll
        for (int i = 0; i < (BM * 8) / 256; i++) {       // 1024 16B chunks for A
            int idx = tid + i * 256, row = idx >> 3, c = idx & 7;
            cp16(sA + swz(row * 128 + c * 16), Ap + (size_t)(m0 + row) * Kseg + kk + c * 8);
        }
#pragma unroll
        for (int i = 0; i < (BN * 8) / 256; i++) {       // 2048 16B chunks for B
            int idx = tid + i * 256, row = idx >> 3, c = idx & 7;
            cp16(sB + swz(row * 128 + c * 16), Bp + (size_t)(n0 + row) * Kseg + kk + c * 8);
        }
        cp_commit();
    };

    float acc[4][8][4];
#pragma unroll
    for (int i = 0; i < 4; i++)
#pragma unroll
        for (int j = 0; j < 8; j++)
#pragma unroll
            for (int k = 0; k < 4; k++) acc[i][j][k] = 0.f;

    load_it(0, 0);
    load_it(1, 1);

    for (int it = 0; it < NITER; it++) {
        if (it + 1 < NITER) cp_wait<1>(); else cp_wait<0>();
        __syncthreads();
        if (it + 2 < NITER) load_it(it + 2, (it + 2) % NSTAGE);

        uint32_t sA = sbase + (it % NSTAGE) * STAGE_BYTES;
        uint32_t sB = sA + SMEM_A_BYTES;
#pragma unroll
        for (int ks = 0; ks < BK / 16; ks++) {
            int kk = ks * 16;
            uint32_t a[4][4], b[4][4];
#pragma unroll
            for (int mi = 0; mi < 4; mi++)
                ldsm4(a[mi], sA + swz((wm + mi * 16 + (lane & 15)) * 128 +
                                      (kk + (lane >> 4) * 8) * 2));
#pragma unroll
            for (int nj = 0; nj < 4; nj++)
                ldsm4(b[nj], sB + swz((wn + nj * 16 + ((lane >> 4) << 3) + (lane & 7)) * 128 +
                                      (kk + ((lane >> 3) & 1) * 8) * 2));
#pragma unroll
            for (int mi = 0; mi < 4; mi++)
#pragma unroll
                for (int nj = 0; nj < 8; nj++)
                    mma16816(acc[mi][nj], a[mi], &b[nj >> 1][(nj & 1) * 2]);
        }
        __syncthreads();
    }

    // epilogue: fp32 accumulators -> C
#pragma unroll
    for (int mi = 0; mi < 4; mi++) {
#pragma unroll
        for (int nj = 0; nj < 8; nj++) {
            int r0 = m0 + wm + mi * 16 + (lane >> 2);
            int col = n0 + wn + nj * 8 + (lane & 3) * 2;
            float2 v0 = make_float2(acc[mi][nj][0], acc[mi][nj][1]);
            float2 v1 = make_float2(acc[mi][nj][2], acc[mi][nj][3]);
            *reinterpret_cast<float2*>(C + (size_t)r0 * ldc + col) = v0;
            *reinterpret_cast<float2*>(C + (size_t)(r0 + 8) * ldc + col) = v1;
        }
    }
}

__global__ __launch_bounds__(256) void softmax_split_kernel() {
    const int r = blockIdx.x, tid = threadIdx.x;
    const float* Srow = g_S + (size_t)r * SEQ;
    __shared__ float red[8];
    float v[16];
    float mx = -3.4e38f;
#pragma unroll
    for (int i = 0; i < 16; i++) { v[i] = Srow[tid + i * 256]; mx = fmaxf(mx, v[i]); }
#pragma unroll
    for (int o = 16; o; o >>= 1) mx = fmaxf(mx, __shfl_xor_sync(0xffffffffu, mx, o));
    if ((tid & 31) == 0) red[tid >> 5] = mx;
    __syncthreads();
    mx = red[0];
#pragma unroll
    for (int w = 1; w < 8; w++) mx = fmaxf(mx, red[w]);
    float sum = 0.f;
#pragma unroll
    for (int i = 0; i < 16; i++) { v[i] = __expf(v[i] - mx); sum += v[i]; }
#pragma unroll
    for (int o = 16; o; o >>= 1) sum += __shfl_xor_sync(0xffffffffu, sum, o);
    __syncthreads();
    if ((tid & 31) == 0) red[tid >> 5] = sum;
    __syncthreads();
    sum = 0.f;
#pragma unroll
    for (int w = 0; w < 8; w++) sum += red[w];
    float inv = 1.f / sum;
#pragma unroll
    for (int i = 0; i < 16; i++) {
        float p = v[i] * inv;
        __nv_bfloat16 h = __float2bfloat16(p);
        __nv_bfloat16 l = __float2bfloat16(p - __bfloat162float(h));
        size_t o = (size_t)r * SEQ + tid + i * 256;
        g_Phi[o] = h;
        g_Plo[o] = l;
    }
}

extern "C" void kernel_launch(void* const* d_in, const int* in_sizes, int n_in,
                              void* d_out, int out_size) {
    const float* Q = (const float*)d_in[0];
    const float* K = (const float*)d_in[1];
    const float* V = (const float*)d_in[2];
    float* O = (float*)d_out;

    static int smem_set = 0;
    if (!smem_set) {
        cudaFuncSetAttribute(gemm_split_kernel, cudaFuncAttributeMaxDynamicSharedMemorySize,
                             SMEM_TOTAL);
        smem_set = 1;
    }

    split_kernel<<<(SEQ * DIM) / (4 * 256), 256>>>(Q, 0);
    split_kernel<<<(SEQ * DIM) / (4 * 256), 256>>>(K, 1);
    transpose_split_kernel<<<dim3(DIM / 32, SEQ / 32), 256>>>(V);
    gemm_split_kernel<<<dim3(SEQ / BN, SEQ / BM), 256, SMEM_TOTAL>>>(0, nullptr);
    softmax_split_kernel<<<SEQ, 256>>>();
    gemm_split_kernel<<<dim3(DIM / BN, SEQ / BM), 256, SMEM_TOTAL>>>(1, O);
}

// round 4
// speedup vs baseline: 1.6637x; 1.6637x over previous
#include <cuda_runtime.h>
#include <cuda_bf16.h>
#include <cuda_fp16.h>
#include <cstdint>
#include <cstddef>

#define SEQ 4096
#define DIM 1024
#define BM 128
#define BN 128
#define BK 64
#define NSTAGE 3
#define SMEM_A_BYTES (BM * 128)
#define SMEM_B_BYTES (BN * 128)
#define STAGE_BYTES (SMEM_A_BYTES + SMEM_B_BYTES)
#define SMEM_TOTAL (1024 + NSTAGE * STAGE_BYTES)
#define PSCALE 16384.0f

__device__ __align__(256) __nv_bfloat16 g_Qhi[(size_t)SEQ * DIM];
__device__ __align__(256) __nv_bfloat16 g_Qlo[(size_t)SEQ * DIM];
__device__ __align__(256) __nv_bfloat16 g_Khi[(size_t)SEQ * DIM];
__device__ __align__(256) __nv_bfloat16 g_Klo[(size_t)SEQ * DIM];
__device__ __align__(256) __half g_Vt16[(size_t)DIM * SEQ];
__device__ __align__(256) float g_S[(size_t)SEQ * SEQ];
__device__ __align__(256) __half g_P16[(size_t)SEQ * SEQ];

__device__ __forceinline__ uint32_t smem_u32(const void* p) {
    uint32_t a;
    asm("{ .reg .u64 t; cvta.to.shared.u64 t, %1; cvt.u32.u64 %0, t; }" : "=r"(a) : "l"(p));
    return a;
}
__device__ __forceinline__ uint32_t swz(uint32_t b) { return b ^ ((b >> 3) & 0x70u); }
__device__ __forceinline__ void cp16(uint32_t dst, const void* src) {
    asm volatile("cp.async.cg.shared.global [%0], [%1], 16;" :: "r"(dst), "l"(src));
}
__device__ __forceinline__ void cp_commit() { asm volatile("cp.async.commit_group;"); }
template <int N> __device__ __forceinline__ void cp_wait() {
    asm volatile("cp.async.wait_group %0;" :: "n"(N));
}
__device__ __forceinline__ void ldsm4(uint32_t* r, uint32_t a) {
    asm volatile("ldmatrix.sync.aligned.m8n8.x4.shared.b16 {%0,%1,%2,%3}, [%4];"
                 : "=r"(r[0]), "=r"(r[1]), "=r"(r[2]), "=r"(r[3]) : "r"(a));
}
__device__ __forceinline__ void mma_bf16(float* c, const uint32_t* a, const uint32_t* b) {
    asm volatile(
        "mma.sync.aligned.m16n8k16.row.col.f32.bf16.bf16.f32 "
        "{%0,%1,%2,%3}, {%4,%5,%6,%7}, {%8,%9}, {%0,%1,%2,%3};"
        : "+f"(c[0]), "+f"(c[1]), "+f"(c[2]), "+f"(c[3])
        : "r"(a[0]), "r"(a[1]), "r"(a[2]), "r"(a[3]), "r"(b[0]), "r"(b[1]));
}
__device__ __forceinline__ void mma_f16(float* c, const uint32_t* a, const uint32_t* b) {
    asm volatile(
        "mma.sync.aligned.m16n8k16.row.col.f32.f16.f16.f32 "
        "{%0,%1,%2,%3}, {%4,%5,%6,%7}, {%8,%9}, {%0,%1,%2,%3};"
        : "+f"(c[0]), "+f"(c[1]), "+f"(c[2]), "+f"(c[3])
        : "r"(a[0]), "r"(a[1]), "r"(a[2]), "r"(a[3]), "r"(b[0]), "r"(b[1]));
}

__global__ __launch_bounds__(256) void split_kernel(const float* __restrict__ X, int which) {
    __nv_bfloat16* hi = which ? g_Khi : g_Qhi;
    __nv_bfloat16* lo = which ? g_Klo : g_Qlo;
    size_t i = (size_t)blockIdx.x * 256 + threadIdx.x;
    float4 x = reinterpret_cast<const float4*>(X)[i];
    float xs[4] = {x.x, x.y, x.z, x.w};
    uint32_t hw[4], lw[4];
#pragma unroll
    for (int k = 0; k < 4; k++) {
        __nv_bfloat16 h = __float2bfloat16(xs[k]);
        __nv_bfloat16 l = __float2bfloat16(xs[k] - __bfloat162float(h));
        hw[k] = __bfloat16_as_ushort(h);
        lw[k] = __bfloat16_as_ushort(l);
    }
    reinterpret_cast<uint2*>(hi)[i] = make_uint2(hw[0] | (hw[1] << 16), hw[2] | (hw[3] << 16));
    reinterpret_cast<uint2*>(lo)[i] = make_uint2(lw[0] | (lw[1] << 16), lw[2] | (lw[3] << 16));
}

__global__ __launch_bounds__(256) void transpose_kernel(const float* __restrict__ V) {
    __shared__ float tile[32][33];
    int tx = threadIdx.x & 31, ty = threadIdx.x >> 5;
    int d0 = blockIdx.x * 32, s0 = blockIdx.y * 32;
#pragma unroll
    for (int j = 0; j < 4; j++)
        tile[ty + j * 8][tx] = V[(size_t)(s0 + ty + j * 8) * DIM + d0 + tx];
    __syncthreads();
#pragma unroll
    for (int j = 0; j < 4; j++) {
        int r = ty + j * 8;
        g_Vt16[(size_t)(d0 + r) * SEQ + s0 + tx] = __float2half_rn(tile[tx][r]);
    }
}

// MODE 0: S = Qhi*Khi^T + Qhi*Klo^T + Qlo*Khi^T  (bf16, Kseg=DIM)
// MODE 1: O = (P16 * Vt16^T) / PSCALE            (f16,  Kseg=SEQ)
template <int MODE>
__global__ __launch_bounds__(256, 2) void gemm_kernel(float* __restrict__ Cout) {
    extern __shared__ __align__(16) char dynsmem[];
    uint32_t sbase = (smem_u32(dynsmem) + 1023u) & ~1023u;
    const int tid = threadIdx.x;
    const int warp = tid >> 5, lane = tid & 31;
    const int wm = (warp & 1) * 64;
    const int wn = (warp >> 1) * 32;
    constexpr int Kseg = MODE ? SEQ : DIM;
    constexpr int segIters = Kseg / BK;
    constexpr int NITER = MODE ? segIters : 3 * segIters;
    const int m0 = blockIdx.y * BM;
    const int n0 = blockIdx.x * BN;
    constexpr int ldc = MODE ? DIM : SEQ;
    float* C = MODE ? Cout : g_S;

    auto load_it = [&](int it, int buf) {
        const uint16_t *Ap, *Bp;
        if (MODE == 1) {
            Ap = (const uint16_t*)g_P16;
            Bp = (const uint16_t*)g_Vt16;
        } else {
            int seg = it / segIters;
            if (seg == 0)      { Ap = (const uint16_t*)g_Qhi; Bp = (const uint16_t*)g_Khi; }
            else if (seg == 1) { Ap = (const uint16_t*)g_Qhi; Bp = (const uint16_t*)g_Klo; }
            else               { Ap = (const uint16_t*)g_Qlo; Bp = (const uint16_t*)g_Khi; }
        }
        int kk = (it % segIters) * BK;
        uint32_t sA = sbase + buf * STAGE_BYTES;
        uint32_t sB = sA + SMEM_A_BYTES;
#pragma unroll
        for (int i = 0; i < (BM * 8) / 256; i++) {
            int idx = tid + i * 256, row = idx >> 3, c = idx & 7;
            cp16(sA + swz(row * 128 + c * 16), Ap + (size_t)(m0 + row) * Kseg + kk + c * 8);
        }
#pragma unroll
        for (int i = 0; i < (BN * 8) / 256; i++) {
            int idx = tid + i * 256, row = idx >> 3, c = idx & 7;
            cp16(sB + swz(row * 128 + c * 16), Bp + (size_t)(n0 + row) * Kseg + kk + c * 8);
        }
        cp_commit();
    };

    float acc[4][4][4];
#pragma unroll
    for (int i = 0; i < 4; i++)
#pragma unroll
        for (int j = 0; j < 4; j++)
#pragma unroll
            for (int k = 0; k < 4; k++) acc[i][j][k] = 0.f;

    load_it(0, 0);
    load_it(1, 1);

    for (int it = 0; it < NITER; it++) {
        if (it + 1 < NITER) cp_wait<1>(); else cp_wait<0>();
        __syncthreads();
        if (it + 2 < NITER) load_it(it + 2, (it + 2) % NSTAGE);

        uint32_t sA = sbase + (it % NSTAGE) * STAGE_BYTES;
        uint32_t sB = sA + SMEM_A_BYTES;
#pragma unroll
        for (int ks = 0; ks < BK / 16; ks++) {
            int kk = ks * 16;
            uint32_t a[4][4], b[2][4];
#pragma unroll
            for (int mi = 0; mi < 4; mi++)
                ldsm4(a[mi], sA + swz((wm + mi * 16 + (lane & 15)) * 128 +
                                      (kk + (lane >> 4) * 8) * 2));
#pragma unroll
            for (int nj = 0; nj < 2; nj++)
                ldsm4(b[nj], sB + swz((wn + nj * 16 + ((lane >> 4) << 3) + (lane & 7)) * 128 +
                                      (kk + ((lane >> 3) & 1) * 8) * 2));
#pragma unroll
            for (int mi = 0; mi < 4; mi++)
#pragma unroll
                for (int nj = 0; nj < 4; nj++) {
                    if (MODE) mma_f16(acc[mi][nj], a[mi], &b[nj >> 1][(nj & 1) * 2]);
                    else      mma_bf16(acc[mi][nj], a[mi], &b[nj >> 1][(nj & 1) * 2]);
                }
        }
    }

#pragma unroll
    for (int mi = 0; mi < 4; mi++) {
#pragma unroll
        for (int nj = 0; nj < 4; nj++) {
            int r0 = m0 + wm + mi * 16 + (lane >> 2);
            int col = n0 + wn + nj * 8 + (lane & 3) * 2;
            float s = MODE ? (1.0f / PSCALE) : 1.0f;
            float2 v0 = make_float2(acc[mi][nj][0] * s, acc[mi][nj][1] * s);
            float2 v1 = make_float2(acc[mi][nj][2] * s, acc[mi][nj][3] * s);
            *reinterpret_cast<float2*>(C + (size_t)r0 * ldc + col) = v0;
            *reinterpret_cast<float2*>(C + (size_t)(r0 + 8) * ldc + col) = v1;
        }
    }
}

__global__ __launch_bounds__(256) void softmax_kernel() {
    const int r = blockIdx.x, tid = threadIdx.x;
    const float* Srow = g_S + (size_t)r * SEQ;
    __shared__ float red[8];
    float v[16];
    float mx = -3.4e38f;
#pragma unroll
    for (int i = 0; i < 16; i++) { v[i] = Srow[tid + i * 256]; mx = fmaxf(mx, v[i]); }
#pragma unroll
    for (int o = 16; o; o >>= 1) mx = fmaxf(mx, __shfl_xor_sync(0xffffffffu, mx, o));
    if ((tid & 31) == 0) red[tid >> 5] = mx;
    __syncthreads();
    mx = red[0];
#pragma unroll
    for (int w = 1; w < 8; w++) mx = fmaxf(mx, red[w]);
    float sum = 0.f;
#pragma unroll
    for (int i = 0; i < 16; i++) { v[i] = __expf(v[i] - mx); sum += v[i]; }
#pragma unroll
    for (int o = 16; o; o >>= 1) sum += __shfl_xor_sync(0xffffffffu, sum, o);
    __syncthreads();
    if ((tid & 31) == 0) red[tid >> 5] = sum;
    __syncthreads();
    sum = 0.f;
#pragma unroll
    for (int w = 0; w < 8; w++) sum += red[w];
    float inv = PSCALE / sum;
    __half* Prow = g_P16 + (size_t)r * SEQ;
#pragma unroll
    for (int i = 0; i < 8; i++) {
        __half2 h2 = __floats2half2_rn(v[2 * i] * inv, v[2 * i + 1] * inv);
        // v[2i], v[2i+1] are columns tid+2i*256, tid+(2i+1)*256 — not adjacent; store singly
        Prow[tid + (2 * i) * 256] = __low2half(h2);
        Prow[tid + (2 * i + 1) * 256] = __high2half(h2);
    }
}

extern "C" void kernel_launch(void* const* d_in, const int* in_sizes, int n_in,
                              void* d_out, int out_size) {
    const float* Q = (const float*)d_in[0];
    const float* K = (const float*)d_in[1];
    const float* V = (const float*)d_in[2];
    float* O = (float*)d_out;

    static int smem_set = 0;
    if (!smem_set) {
        cudaFuncSetAttribute(gemm_kernel<0>, cudaFuncAttributeMaxDynamicSharedMemorySize,
                             SMEM_TOTAL);
        cudaFuncSetAttribute(gemm_kernel<1>, cudaFuncAttributeMaxDynamicSharedMemorySize,
                             SMEM_TOTAL);
        smem_set = 1;
    }

    split_kernel<<<(SEQ * DIM) / (4 * 256), 256>>>(Q, 0);
    split_kernel<<<(SEQ * DIM) / (4 * 256), 256>>>(K, 1);
    transpose_kernel<<<dim3(DIM / 32, SEQ / 32), 256>>>(V);
    gemm_kernel<0><<<dim3(SEQ / BN, SEQ / BM), 256, SMEM_TOTAL>>>(nullptr);
    softmax_kernel<<<SEQ, 256>>>();
    gemm_kernel<1><<<dim3(DIM / BN, SEQ / BM), 256, SMEM_TOTAL>>>(O);
}